// round 8
// baseline (speedup 1.0000x reference)
#include <cuda_runtime.h>
#include <cuda_fp16.h>
#include <stdint.h>

#define BATCH   16
#define CH      256
#define RES     128
#define LATENT  512
#define KTOT    2304      // 9 taps * 256
#define SQRT2F  1.4142135623730951f

// ---------------- scratch (device globals; no allocation allowed) ----------
__device__ __half g_xt[(size_t)BATCH * RES * RES * CH];  // [b][h][w][c] modulated, fp16
__device__ __half g_wt[(size_t)CH * KTOT];               // [o][tap][i], fp16
__device__ float  g_style[BATCH * CH];
__device__ float  g_wsq[CH * CH];                        // TRANSPOSED: [i][o]
__device__ float  g_demod[BATCH * CH];

// ---------------- helpers --------------------------------------------------
__device__ __forceinline__ uint32_t s2u(const void* p) {
    uint32_t a;
    asm("{ .reg .u64 t; cvta.to.shared.u64 t, %1; cvt.u32.u64 %0, t; }" : "=r"(a) : "l"(p));
    return a;
}
__device__ __forceinline__ uint32_t swz(uint32_t off) {   // 128B-row XOR swizzle
    return off ^ ((off >> 3) & 0x70);
}
__device__ __forceinline__ void cp16(uint32_t dst, const void* src, uint32_t sz) {
    asm volatile("cp.async.cg.shared.global [%0], [%1], 16, %2;"
                 :: "r"(dst), "l"(src), "r"(sz));
}
__device__ __forceinline__ void cp_commit() { asm volatile("cp.async.commit_group;"); }
#define CP_WAIT(n) asm volatile("cp.async.wait_group %0;" :: "n"(n))

__device__ __forceinline__ void ldm4(uint32_t* r, uint32_t addr) {
    asm volatile("ldmatrix.sync.aligned.m8n8.x4.shared.b16 {%0,%1,%2,%3}, [%4];"
                 : "=r"(r[0]), "=r"(r[1]), "=r"(r[2]), "=r"(r[3]) : "r"(addr));
}
__device__ __forceinline__ void mma16816(float* d, const uint32_t* a,
                                         uint32_t b0, uint32_t b1) {
    asm volatile("mma.sync.aligned.m16n8k16.row.col.f32.f16.f16.f32 "
                 "{%0,%1,%2,%3}, {%4,%5,%6,%7}, {%8,%9}, {%0,%1,%2,%3};"
                 : "+f"(d[0]), "+f"(d[1]), "+f"(d[2]), "+f"(d[3])
                 : "r"(a[0]), "r"(a[1]), "r"(a[2]), "r"(a[3]), "r"(b0), "r"(b1));
}

// ---------------- prep kernels (parallel) -----------------------------------
__global__ void prep_style_wsq(const float* __restrict__ latent,
                               const float* __restrict__ aff_w,
                               const float* __restrict__ aff_b,
                               const float* __restrict__ conv_w) {
    int tid = blockIdx.x * blockDim.x + threadIdx.x;
    if (tid < BATCH * CH) {
        int b = tid / CH, i = tid % CH;
        const float* lrow = latent + (size_t)b * LATENT;
        const float* wrow = aff_w + (size_t)i * LATENT;
        float acc = 0.f;
        #pragma unroll 4
        for (int j = 0; j < LATENT; ++j) acc += lrow[j] * wrow[j];
        g_style[tid] = acc * 0.04419417382415922f /* sqrt(1/512) */ + aff_b[i];
    }
    int t2 = tid - BATCH * CH;
    if (t2 >= 0 && t2 < CH * CH) {
        int o = t2 / CH, i = t2 % CH;
        const float* w = conv_w + (size_t)t2 * 9;
        float a = 0.f;
        #pragma unroll
        for (int j = 0; j < 9; ++j) a += w[j] * w[j];
        g_wsq[i * CH + o] = a;                 // transposed for coalesced demod
    }
}

// blocks [0,16): demod per batch.  blocks [16, 16+2304): weight transpose.
__global__ void __launch_bounds__(256) prep_demod_wt(const float* __restrict__ conv_w) {
    int blk = blockIdx.x;
    int tid = threadIdx.x;
    if (blk < BATCH) {
        __shared__ float sty_s[CH];
        int b = blk;
        sty_s[tid] = g_style[b * CH + tid];
        __syncthreads();
        int o = tid;
        float d = 1e-8f;
        #pragma unroll 4
        for (int i = 0; i < CH; ++i) {
            float s = sty_s[i];
            d += g_wsq[i * CH + o] * s * s;    // coalesced across o
        }
        g_demod[b * CH + o] = rsqrtf(d);
    } else {
        int w = blk - BATCH;                   // 0..2303 = o*9 + tap
        int o = w / 9, tap = w - o * 9;
        g_wt[(size_t)o * KTOT + tap * CH + tid] =
            __float2half(conv_w[((size_t)o * CH + tid) * 9 + tap]);
    }
}

// content NCHW -> NHWC (fp16), multiplied by style.  Each block: 2 channel tiles.
__global__ void __launch_bounds__(256) mod_transpose(const float* __restrict__ content) {
    __shared__ float tile[2][32][33];
    int bx = blockIdx.x;
    int wt_ = bx & 3;
    int p   = (bx >> 2) & 3;
    int h   = (bx >> 4) & 127;
    int b   = bx >> 11;
    int w0 = wt_ * 32;
    int tx = threadIdx.x & 31, ty = threadIdx.x >> 5;
    #pragma unroll
    for (int tt = 0; tt < 2; ++tt) {
        int c0 = (2 * p + tt) * 32;
        #pragma unroll
        for (int r = 0; r < 4; ++r) {
            int cl = ty + r * 8;
            int c  = c0 + cl;
            tile[tt][cl][tx] = content[(((size_t)b * CH + c) * RES + h) * RES + (w0 + tx)]
                               * g_style[b * CH + c];
        }
    }
    __syncthreads();
    #pragma unroll
    for (int tt = 0; tt < 2; ++tt) {
        int c0 = (2 * p + tt) * 32;
        #pragma unroll
        for (int r = 0; r < 4; ++r) {
            int wl = ty + r * 8;
            g_xt[(((size_t)b * RES + h) * RES + (w0 + wl)) * CH + (c0 + tx)] =
                __float2half(tile[tt][tx][wl]);
        }
    }
}

// ---------------- main conv GEMM (mma.sync fp16, A-halo reuse) -------------
// CTA: M=128 (one (b,h) pixel row), N=256 (all cout).
// K order: super g = kh*4+ic64 (12), inner kw (3).  A tile per g: 130 pixel
// rows (w=-1..128) x 64ch; kw taps read it with ldmatrix row offset +kw.
#define SM_DEMOD   0
#define SM_BIAS    1024
#define SM_A       2048
#define A_SLOT     17408          // 130 rows x 128B, padded to 17KB
#define SM_B       (SM_A + 2 * A_SLOT)       // 36864
#define B_SLOT     32768
#define SMEM_TOTAL (SM_B + 4 * B_SLOT)       // 167936
#define SM_D       2048           // epilogue staging reuses A/B area

__device__ __forceinline__ void load_A(uint32_t smem_base, int g, int b, int h, int tid) {
    int kh = g >> 2, ic = g & 3;
    int hin = h + kh - 1;
    bool hok = (unsigned)hin < RES;
    int hc = hok ? hin : 0;
    uint32_t base = smem_base + SM_A + (g & 1) * A_SLOT;
    #pragma unroll 5
    for (int v = tid; v < 1040; v += 256) {     // 130 rows x 8 segs
        int row = v >> 3, seg = v & 7;
        int win = row - 1;
        bool ok = hok && ((unsigned)win < RES);
        int wc = ok ? win : 0;
        const __half* src = g_xt + (((size_t)(b * RES + hc) * RES + wc) * CH
                                    + ic * 64 + seg * 8);
        cp16(base + swz((uint32_t)(row * 128 + seg * 16)), src, ok ? 16u : 0u);
    }
}

__device__ __forceinline__ void load_B(uint32_t smem_base, int c, int tid) {
    int g = c / 3, kw = c - g * 3;
    int kh = g >> 2, ic = g & 3;
    int tap = kh * 3 + kw;
    uint32_t base = smem_base + SM_B + (c & 3) * B_SLOT;
    #pragma unroll
    for (int j = 0; j < 8; ++j) {
        int v = tid + j * 256;
        int row = v >> 3, seg = v & 7;
        const __half* src = g_wt + ((size_t)row * KTOT + tap * 256 + ic * 64 + seg * 8);
        cp16(base + swz((uint32_t)(row * 128 + seg * 16)), src, 16u);
    }
}

__global__ void __launch_bounds__(256, 1)
conv_gemm(const float* __restrict__ noise,
          const float* __restrict__ noise_w_p,
          const float* __restrict__ bias,
          float* __restrict__ out) {
    extern __shared__ __align__(1024) char smem[];
    uint32_t smem_base = s2u(smem);
    int tid = threadIdx.x;
    int wid = tid >> 5, lid = tid & 31;
    int wm = wid & 1, wn = wid >> 1;

    int bx = blockIdx.x;            // 2048 CTAs: b (16) x h (128)
    int b  = bx >> 7;
    int h  = bx & 127;

    float* demod_s = (float*)(smem + SM_DEMOD);
    float* bias_s  = (float*)(smem + SM_BIAS);
    for (int k = tid; k < CH; k += 256) {
        demod_s[k] = g_demod[b * CH + k];
        bias_s[k]  = bias[k];
    }

    float acc[4][8][4];
    #pragma unroll
    for (int i = 0; i < 4; ++i)
        #pragma unroll
        for (int j = 0; j < 8; ++j)
            #pragma unroll
            for (int k = 0; k < 4; ++k) acc[i][j][k] = 0.f;

    // prologue groups: {A0,B0}, {B1}, {B2}
    load_A(smem_base, 0, b, h, tid); load_B(smem_base, 0, tid); cp_commit();
    load_B(smem_base, 1, tid); cp_commit();
    load_B(smem_base, 2, tid); cp_commit();

    for (int g = 0; g < 12; ++g) {
        uint32_t abase = smem_base + SM_A + (g & 1) * A_SLOT;
        #pragma unroll
        for (int kw = 0; kw < 3; ++kw) {
            int c = g * 3 + kw;
            if (c <= 33) { CP_WAIT(2); }
            else if (c == 34) { CP_WAIT(1); }
            else { CP_WAIT(0); }
            __syncthreads();

            int cn = c + 3;
            if (cn < 36) {
                if (cn % 3 == 0) load_A(smem_base, cn / 3, b, h, tid);
                load_B(smem_base, cn, tid);
                cp_commit();
            }

            uint32_t bbase = smem_base + SM_B + (c & 3) * B_SLOT;
            #pragma unroll
            for (int kk = 0; kk < 4; ++kk) {        // 4 x k16
                uint32_t afr[4][4];
                #pragma unroll
                for (int mi = 0; mi < 4; ++mi) {
                    int row = kw + wm * 64 + mi * 16 + (lid & 15);
                    int col = kk * 32 + (lid >> 4) * 16;
                    ldm4(afr[mi], abase + swz((uint32_t)(row * 128 + col)));
                }
                uint32_t bfr[4][4];
                #pragma unroll
                for (int nj = 0; nj < 4; ++nj) {
                    int row = wn * 64 + nj * 16 + (lid & 7) + ((lid >> 4) << 3);
                    int col = kk * 32 + ((lid >> 3) & 1) * 16;
                    ldm4(bfr[nj], bbase + swz((uint32_t)(row * 128 + col)));
                }
                #pragma unroll
                for (int mi = 0; mi < 4; ++mi)
                    #pragma unroll
                    for (int nj = 0; nj < 4; ++nj) {
                        mma16816(acc[mi][2 * nj],     afr[mi], bfr[nj][0], bfr[nj][1]);
                        mma16816(acc[mi][2 * nj + 1], afr[mi], bfr[nj][2], bfr[nj][3]);
                    }
            }
        }
    }
    __syncthreads();

    // stage D into smem as [n][m] floats for coalesced NCHW output
    float* D = (float*)(smem + SM_D);
    int gq = lid >> 2, tig = lid & 3;
    #pragma unroll
    for (int mi = 0; mi < 4; ++mi) {
        int m0 = wm * 64 + mi * 16 + gq;
        #pragma unroll
        for (int ns = 0; ns < 8; ++ns) {
            int n0 = wn * 64 + ns * 8 + 2 * tig;
            float* p = acc[mi][ns];
            D[n0 * 128 + m0]           = p[0];
            D[(n0 + 1) * 128 + m0]     = p[1];
            D[n0 * 128 + m0 + 8]       = p[2];
            D[(n0 + 1) * 128 + m0 + 8] = p[3];
        }
    }
    __syncthreads();

    float nwv = noise_w_p[0];
    const float4* nz4 = (const float4*)(noise + ((size_t)b * RES + h) * RES);
    #pragma unroll 4
    for (int t = tid; t < 8192; t += 256) {       // 8192 float4 = 256n x 128m
        int n  = t >> 5;
        int m4 = (t & 31);
        float4 v  = ((const float4*)D)[t];
        float4 nz = nz4[m4];
        float dm = demod_s[n], bs = bias_s[n];
        float4 o;
        o.x = v.x * dm + nwv * nz.x + bs;
        o.y = v.y * dm + nwv * nz.y + bs;
        o.z = v.z * dm + nwv * nz.z + bs;
        o.w = v.w * dm + nwv * nz.w + bs;
        o.x = (o.x > 0.f ? o.x : 0.2f * o.x) * SQRT2F;
        o.y = (o.y > 0.f ? o.y : 0.2f * o.y) * SQRT2F;
        o.z = (o.z > 0.f ? o.z : 0.2f * o.z) * SQRT2F;
        o.w = (o.w > 0.f ? o.w : 0.2f * o.w) * SQRT2F;
        ((float4*)(out + (((size_t)b * CH + n) * RES + h) * RES))[m4] = o;
    }
}

// ---------------- launch ---------------------------------------------------
extern "C" void kernel_launch(void* const* d_in, const int* in_sizes, int n_in,
                              void* d_out, int out_size) {
    const float* content = (const float*)d_in[0];
    const float* latent  = (const float*)d_in[1];
    const float* noise   = (const float*)d_in[2];
    const float* aff_w   = (const float*)d_in[3];
    const float* aff_b   = (const float*)d_in[4];
    const float* conv_w  = (const float*)d_in[5];
    const float* bias    = (const float*)d_in[6];
    const float* nw      = (const float*)d_in[7];
    float* out = (float*)d_out;

    prep_style_wsq<<<(BATCH * CH + CH * CH + 255) / 256, 256>>>(latent, aff_w, aff_b, conv_w);
    prep_demod_wt<<<BATCH + CH * 9, 256>>>(conv_w);
    mod_transpose<<<BATCH * RES * 4 * 4, 256>>>(content);

    cudaFuncSetAttribute(conv_gemm, cudaFuncAttributeMaxDynamicSharedMemorySize, SMEM_TOTAL);
    conv_gemm<<<2048, 256, SMEM_TOTAL>>>(noise, nw, bias, out);
}

// round 9
// speedup vs baseline: 1.6307x; 1.6307x over previous
#include <cuda_runtime.h>
#include <cuda_fp16.h>
#include <stdint.h>

#define BATCH   16
#define CH      256
#define RES     128
#define LATENT  512
#define KTOT    2304      // 9 taps * 256
#define SQRT2F  1.4142135623730951f

// ---------------- scratch (device globals; no allocation allowed) ----------
__device__ __half g_xt[(size_t)BATCH * RES * RES * CH];  // [b][h][w][c] modulated, fp16
__device__ __half g_wt[(size_t)CH * KTOT];               // [o][tap][i], fp16
__device__ float  g_style[BATCH * CH];
__device__ float  g_wsq[CH * CH];                        // TRANSPOSED: [i][o]
__device__ float  g_demod[BATCH * CH];

// ---------------- helpers --------------------------------------------------
__device__ __forceinline__ uint32_t s2u(const void* p) {
    uint32_t a;
    asm("{ .reg .u64 t; cvta.to.shared.u64 t, %1; cvt.u32.u64 %0, t; }" : "=r"(a) : "l"(p));
    return a;
}
__device__ __forceinline__ uint32_t swz(uint32_t off) {   // 128B-row XOR swizzle
    return off ^ ((off >> 3) & 0x70);
}
__device__ __forceinline__ void cp16(uint32_t dst, const void* src, uint32_t sz) {
    asm volatile("cp.async.cg.shared.global [%0], [%1], 16, %2;"
                 :: "r"(dst), "l"(src), "r"(sz));
}
__device__ __forceinline__ void cp_commit() { asm volatile("cp.async.commit_group;"); }
#define CP_WAIT(n) asm volatile("cp.async.wait_group %0;" :: "n"(n))

__device__ __forceinline__ void ldm4(uint32_t* r, uint32_t addr) {
    asm volatile("ldmatrix.sync.aligned.m8n8.x4.shared.b16 {%0,%1,%2,%3}, [%4];"
                 : "=r"(r[0]), "=r"(r[1]), "=r"(r[2]), "=r"(r[3]) : "r"(addr));
}
__device__ __forceinline__ void mma16816(float* d, const uint32_t* a,
                                         uint32_t b0, uint32_t b1) {
    asm volatile("mma.sync.aligned.m16n8k16.row.col.f32.f16.f16.f32 "
                 "{%0,%1,%2,%3}, {%4,%5,%6,%7}, {%8,%9}, {%0,%1,%2,%3};"
                 : "+f"(d[0]), "+f"(d[1]), "+f"(d[2]), "+f"(d[3])
                 : "r"(a[0]), "r"(a[1]), "r"(a[2]), "r"(a[3]), "r"(b0), "r"(b1));
}

// ---------------- prep kernels (parallel) -----------------------------------
__global__ void prep_style_wsq(const float* __restrict__ latent,
                               const float* __restrict__ aff_w,
                               const float* __restrict__ aff_b,
                               const float* __restrict__ conv_w) {
    int tid = blockIdx.x * blockDim.x + threadIdx.x;
    if (tid < BATCH * CH) {
        int b = tid / CH, i = tid % CH;
        const float* lrow = latent + (size_t)b * LATENT;
        const float* wrow = aff_w + (size_t)i * LATENT;
        float acc = 0.f;
        #pragma unroll 4
        for (int j = 0; j < LATENT; ++j) acc += lrow[j] * wrow[j];
        g_style[tid] = acc * 0.04419417382415922f /* sqrt(1/512) */ + aff_b[i];
    }
    int t2 = tid - BATCH * CH;
    if (t2 >= 0 && t2 < CH * CH) {
        int o = t2 / CH, i = t2 % CH;
        const float* w = conv_w + (size_t)t2 * 9;
        float a = 0.f;
        #pragma unroll
        for (int j = 0; j < 9; ++j) a += w[j] * w[j];
        g_wsq[i * CH + o] = a;                 // transposed for coalesced demod
    }
}

// blocks [0,16): demod per batch.  blocks [16, 16+2304): weight transpose.
__global__ void __launch_bounds__(256) prep_demod_wt(const float* __restrict__ conv_w) {
    int blk = blockIdx.x;
    int tid = threadIdx.x;
    if (blk < BATCH) {
        __shared__ float sty_s[CH];
        int b = blk;
        sty_s[tid] = g_style[b * CH + tid];
        __syncthreads();
        int o = tid;
        float d = 1e-8f;
        #pragma unroll 4
        for (int i = 0; i < CH; ++i) {
            float s = sty_s[i];
            d += g_wsq[i * CH + o] * s * s;    // coalesced across o
        }
        g_demod[b * CH + o] = rsqrtf(d);
    } else {
        int w = blk - BATCH;                   // 0..2303 = o*9 + tap
        int o = w / 9, tap = w - o * 9;
        g_wt[(size_t)o * KTOT + tap * CH + tid] =
            __float2half(conv_w[((size_t)o * CH + tid) * 9 + tap]);
    }
}

// content NCHW -> NHWC (fp16), multiplied by style.  Each block: 2 channel tiles.
__global__ void __launch_bounds__(256) mod_transpose(const float* __restrict__ content) {
    __shared__ float tile[2][32][33];
    int bx = blockIdx.x;
    int wt_ = bx & 3;
    int p   = (bx >> 2) & 3;
    int h   = (bx >> 4) & 127;
    int b   = bx >> 11;
    int w0 = wt_ * 32;
    int tx = threadIdx.x & 31, ty = threadIdx.x >> 5;
    #pragma unroll
    for (int tt = 0; tt < 2; ++tt) {
        int c0 = (2 * p + tt) * 32;
        #pragma unroll
        for (int r = 0; r < 4; ++r) {
            int cl = ty + r * 8;
            int c  = c0 + cl;
            tile[tt][cl][tx] = content[(((size_t)b * CH + c) * RES + h) * RES + (w0 + tx)]
                               * g_style[b * CH + c];
        }
    }
    __syncthreads();
    #pragma unroll
    for (int tt = 0; tt < 2; ++tt) {
        int c0 = (2 * p + tt) * 32;
        #pragma unroll
        for (int r = 0; r < 4; ++r) {
            int wl = ty + r * 8;
            g_xt[(((size_t)b * RES + h) * RES + (w0 + wl)) * CH + (c0 + tx)] =
                __float2half(tile[tt][tx][wl]);
        }
    }
}

// ---------------- main conv GEMM (mma.sync fp16, 2 CTAs/SM) ----------------
// CTA: M=128 (one (b,h) pixel row), N=128 (half of cout), K=2304.
// 8 warps = 2(M) x 4(N), warp tile 64x32.  3-stage 32KB ring -> 99KB smem.
#define SM_DEMOD   0              // 128 floats (this CTA's channel half)
#define SM_BIAS    512
#define SM_ST      1024
#define STAGE_SZ   32768          // A 16KB + B 16KB
#define A_OFF(s)   (SM_ST + (s) * STAGE_SZ)
#define B_OFF(s)   (SM_ST + (s) * STAGE_SZ + 16384)
#define SMEM_TOTAL (SM_ST + 3 * STAGE_SZ)     // 99328
#define SM_D       1024           // epilogue staging reuses ring

__device__ __forceinline__ void load_stage(uint32_t smem_base, int step, int slot,
                                           int b, int h, int nh, int tid) {
    int tap = step >> 2;            // 0..8
    int ic0 = (step & 3) * 64;      // channel chunk base
    int kh = tap / 3, kw = tap - kh * 3;
    int hin = h + kh - 1;
    bool hok = (unsigned)hin < RES;
    int hc = hok ? hin : 0;
    uint32_t abase = smem_base + A_OFF(slot);
    uint32_t bbase = smem_base + B_OFF(slot);
    // A: 128 rows (w) x 64 halves (128B)
    #pragma unroll
    for (int j = 0; j < 4; ++j) {
        int v = tid + j * 256;
        int row = v >> 3, seg = v & 7;
        int win = row + kw - 1;
        bool ok = hok && ((unsigned)win < RES);
        int wc = ok ? win : 0;
        const __half* src = g_xt + (((size_t)(b * RES + hc) * RES + wc) * CH
                                    + ic0 + seg * 8);
        cp16(abase + swz((uint32_t)(row * 128 + seg * 16)), src, ok ? 16u : 0u);
    }
    // B: 128 rows (cout half) x 64 halves
    #pragma unroll
    for (int j = 0; j < 4; ++j) {
        int v = tid + j * 256;
        int row = v >> 3, seg = v & 7;
        const __half* src = g_wt + ((size_t)(nh * 128 + row) * KTOT
                                    + tap * 256 + ic0 + seg * 8);
        cp16(bbase + swz((uint32_t)(row * 128 + seg * 16)), src, 16u);
    }
}

__global__ void __launch_bounds__(256, 2)
conv_gemm(const float* __restrict__ noise,
          const float* __restrict__ noise_w_p,
          const float* __restrict__ bias,
          float* __restrict__ out) {
    extern __shared__ __align__(1024) char smem[];
    uint32_t smem_base = s2u(smem);
    int tid = threadIdx.x;
    int wid = tid >> 5, lid = tid & 31;
    int wm = wid & 1, wn = wid >> 1;

    int bx = blockIdx.x;            // 4096 CTAs: b (16) x h (128) x nh (2)
    int nh = bx & 1;
    int h  = (bx >> 1) & 127;
    int b  = bx >> 8;

    float* demod_s = (float*)(smem + SM_DEMOD);
    float* bias_s  = (float*)(smem + SM_BIAS);
    if (tid < 128) {
        demod_s[tid] = g_demod[b * CH + nh * 128 + tid];
        bias_s[tid]  = bias[nh * 128 + tid];
    }

    float acc[4][4][4];
    #pragma unroll
    for (int i = 0; i < 4; ++i)
        #pragma unroll
        for (int j = 0; j < 4; ++j)
            #pragma unroll
            for (int k = 0; k < 4; ++k) acc[i][j][k] = 0.f;

    // prologue: 2 stages in flight
    load_stage(smem_base, 0, 0, b, h, nh, tid); cp_commit();
    load_stage(smem_base, 1, 1, b, h, nh, tid); cp_commit();

    for (int c = 0; c < 36; ++c) {
        if (c < 35) { CP_WAIT(1); } else { CP_WAIT(0); }
        __syncthreads();
        if (c + 2 < 36) {
            load_stage(smem_base, c + 2, (c + 2) % 3, b, h, nh, tid);
            cp_commit();
        }
        int s = c % 3;
        uint32_t abase = smem_base + A_OFF(s);
        uint32_t bbase = smem_base + B_OFF(s);
        #pragma unroll
        for (int kk = 0; kk < 4; ++kk) {        // 4 x k16
            uint32_t afr[4][4];
            #pragma unroll
            for (int mi = 0; mi < 4; ++mi) {
                int row = wm * 64 + mi * 16 + (lid & 15);
                int col = kk * 32 + (lid >> 4) * 16;
                ldm4(afr[mi], abase + swz((uint32_t)(row * 128 + col)));
            }
            uint32_t bfr[2][4];
            #pragma unroll
            for (int nj = 0; nj < 2; ++nj) {
                int row = wn * 32 + nj * 16 + (lid & 7) + ((lid >> 4) << 3);
                int col = kk * 32 + ((lid >> 3) & 1) * 16;
                ldm4(bfr[nj], bbase + swz((uint32_t)(row * 128 + col)));
            }
            #pragma unroll
            for (int mi = 0; mi < 4; ++mi)
                #pragma unroll
                for (int nj = 0; nj < 2; ++nj) {
                    mma16816(acc[mi][2 * nj],     afr[mi], bfr[nj][0], bfr[nj][1]);
                    mma16816(acc[mi][2 * nj + 1], afr[mi], bfr[nj][2], bfr[nj][3]);
                }
        }
    }
    __syncthreads();

    // stage D into smem as [n][m] floats (128 x 128) for coalesced NCHW output
    float* D = (float*)(smem + SM_D);
    int gq = lid >> 2, tig = lid & 3;
    #pragma unroll
    for (int mi = 0; mi < 4; ++mi) {
        int m0 = wm * 64 + mi * 16 + gq;
        #pragma unroll
        for (int ns = 0; ns < 4; ++ns) {
            int n0 = wn * 32 + ns * 8 + 2 * tig;
            float* p = acc[mi][ns];
            D[n0 * 128 + m0]           = p[0];
            D[(n0 + 1) * 128 + m0]     = p[1];
            D[n0 * 128 + m0 + 8]       = p[2];
            D[(n0 + 1) * 128 + m0 + 8] = p[3];
        }
    }
    __syncthreads();

    float nwv = noise_w_p[0];
    const float4* nz4 = (const float4*)(noise + ((size_t)b * RES + h) * RES);
    #pragma unroll 4
    for (int t = tid; t < 4096; t += 256) {       // 4096 float4 = 128n x 128m
        int n  = t >> 5;
        int m4 = (t & 31);
        float4 v  = ((const float4*)D)[t];
        float4 nz = nz4[m4];
        float dm = demod_s[n], bs = bias_s[n];
        float4 o;
        o.x = v.x * dm + nwv * nz.x + bs;
        o.y = v.y * dm + nwv * nz.y + bs;
        o.z = v.z * dm + nwv * nz.z + bs;
        o.w = v.w * dm + nwv * nz.w + bs;
        o.x = (o.x > 0.f ? o.x : 0.2f * o.x) * SQRT2F;
        o.y = (o.y > 0.f ? o.y : 0.2f * o.y) * SQRT2F;
        o.z = (o.z > 0.f ? o.z : 0.2f * o.z) * SQRT2F;
        o.w = (o.w > 0.f ? o.w : 0.2f * o.w) * SQRT2F;
        ((float4*)(out + (((size_t)b * CH + nh * 128 + n) * RES + h) * RES))[m4] = o;
    }
}

// ---------------- launch ---------------------------------------------------
extern "C" void kernel_launch(void* const* d_in, const int* in_sizes, int n_in,
                              void* d_out, int out_size) {
    const float* content = (const float*)d_in[0];
    const float* latent  = (const float*)d_in[1];
    const float* noise   = (const float*)d_in[2];
    const float* aff_w   = (const float*)d_in[3];
    const float* aff_b   = (const float*)d_in[4];
    const float* conv_w  = (const float*)d_in[5];
    const float* bias    = (const float*)d_in[6];
    const float* nw      = (const float*)d_in[7];
    float* out = (float*)d_out;

    prep_style_wsq<<<(BATCH * CH + CH * CH + 255) / 256, 256>>>(latent, aff_w, aff_b, conv_w);
    prep_demod_wt<<<BATCH + CH * 9, 256>>>(conv_w);
    mod_transpose<<<BATCH * RES * 4 * 4, 256>>>(content);

    cudaFuncSetAttribute(conv_gemm, cudaFuncAttributeMaxDynamicSharedMemorySize, SMEM_TOTAL);
    conv_gemm<<<4096, 256, SMEM_TOTAL>>>(noise, nw, bias, out);
}

// round 10
// speedup vs baseline: 1.6434x; 1.0078x over previous
#include <cuda_runtime.h>
#include <cuda_fp16.h>
#include <stdint.h>

#define BATCH   16
#define CH      256
#define RES     128
#define LATENT  512
#define KTOT    2304      // 9 taps * 256
#define SQRT2F  1.4142135623730951f

// ---------------- scratch (device globals; no allocation allowed) ----------
__device__ __half g_xt[(size_t)BATCH * RES * RES * CH];  // [b][h][w][c] modulated, fp16
__device__ __half g_wt[(size_t)CH * KTOT];               // [o][tap][i], fp16
__device__ float  g_style[BATCH * CH];
__device__ float  g_wsq[CH * CH];                        // TRANSPOSED: [i][o]
__device__ float  g_demod[BATCH * CH];

// ---------------- helpers --------------------------------------------------
__device__ __forceinline__ uint32_t s2u(const void* p) {
    uint32_t a;
    asm("{ .reg .u64 t; cvta.to.shared.u64 t, %1; cvt.u32.u64 %0, t; }" : "=r"(a) : "l"(p));
    return a;
}
__device__ __forceinline__ uint32_t swz(uint32_t off) {   // 128B-row XOR swizzle
    return off ^ ((off >> 3) & 0x70);
}
__device__ __forceinline__ void cp16(uint32_t dst, const void* src, uint32_t sz) {
    asm volatile("cp.async.cg.shared.global [%0], [%1], 16, %2;"
                 :: "r"(dst), "l"(src), "r"(sz));
}
__device__ __forceinline__ void cp_commit() { asm volatile("cp.async.commit_group;"); }
#define CP_WAIT(n) asm volatile("cp.async.wait_group %0;" :: "n"(n))

__device__ __forceinline__ void ldm4(uint32_t* r, uint32_t addr) {
    asm volatile("ldmatrix.sync.aligned.m8n8.x4.shared.b16 {%0,%1,%2,%3}, [%4];"
                 : "=r"(r[0]), "=r"(r[1]), "=r"(r[2]), "=r"(r[3]) : "r"(addr));
}
__device__ __forceinline__ void mma16816(float* d, const uint32_t* a,
                                         uint32_t b0, uint32_t b1) {
    asm volatile("mma.sync.aligned.m16n8k16.row.col.f32.f16.f16.f32 "
                 "{%0,%1,%2,%3}, {%4,%5,%6,%7}, {%8,%9}, {%0,%1,%2,%3};"
                 : "+f"(d[0]), "+f"(d[1]), "+f"(d[2]), "+f"(d[3])
                 : "r"(a[0]), "r"(a[1]), "r"(a[2]), "r"(a[3]), "r"(b0), "r"(b1));
}

// ---------------- prep kernels (parallel) -----------------------------------
__global__ void prep_style_wsq(const float* __restrict__ latent,
                               const float* __restrict__ aff_w,
                               const float* __restrict__ aff_b,
                               const float* __restrict__ conv_w) {
    int tid = blockIdx.x * blockDim.x + threadIdx.x;
    if (tid < BATCH * CH) {
        int b = tid / CH, i = tid % CH;
        const float* lrow = latent + (size_t)b * LATENT;
        const float* wrow = aff_w + (size_t)i * LATENT;
        float acc = 0.f;
        #pragma unroll 4
        for (int j = 0; j < LATENT; ++j) acc += lrow[j] * wrow[j];
        g_style[tid] = acc * 0.04419417382415922f /* sqrt(1/512) */ + aff_b[i];
    }
    int t2 = tid - BATCH * CH;
    if (t2 >= 0 && t2 < CH * CH) {
        int o = t2 / CH, i = t2 % CH;
        const float* w = conv_w + (size_t)t2 * 9;
        float a = 0.f;
        #pragma unroll
        for (int j = 0; j < 9; ++j) a += w[j] * w[j];
        g_wsq[i * CH + o] = a;                 // transposed for coalesced demod
    }
}

// blocks [0,16): demod per batch.  blocks [16, 16+2304): weight transpose.
__global__ void __launch_bounds__(256) prep_demod_wt(const float* __restrict__ conv_w) {
    int blk = blockIdx.x;
    int tid = threadIdx.x;
    if (blk < BATCH) {
        __shared__ float sty_s[CH];
        int b = blk;
        sty_s[tid] = g_style[b * CH + tid];
        __syncthreads();
        int o = tid;
        float d = 1e-8f;
        #pragma unroll 4
        for (int i = 0; i < CH; ++i) {
            float s = sty_s[i];
            d += g_wsq[i * CH + o] * s * s;    // coalesced across o
        }
        g_demod[b * CH + o] = rsqrtf(d);
    } else {
        int w = blk - BATCH;                   // 0..2303 = o*9 + tap
        int o = w / 9, tap = w - o * 9;
        g_wt[(size_t)o * KTOT + tap * CH + tid] =
            __float2half(conv_w[((size_t)o * CH + tid) * 9 + tap]);
    }
}

// content NCHW -> NHWC (fp16), multiplied by style.  Each block: 2 channel tiles.
__global__ void __launch_bounds__(256) mod_transpose(const float* __restrict__ content) {
    __shared__ float tile[2][32][33];
    int bx = blockIdx.x;
    int wt_ = bx & 3;
    int p   = (bx >> 2) & 3;
    int h   = (bx >> 4) & 127;
    int b   = bx >> 11;
    int w0 = wt_ * 32;
    int tx = threadIdx.x & 31, ty = threadIdx.x >> 5;
    #pragma unroll
    for (int tt = 0; tt < 2; ++tt) {
        int c0 = (2 * p + tt) * 32;
        #pragma unroll
        for (int r = 0; r < 4; ++r) {
            int cl = ty + r * 8;
            int c  = c0 + cl;
            tile[tt][cl][tx] = content[(((size_t)b * CH + c) * RES + h) * RES + (w0 + tx)]
                               * g_style[b * CH + c];
        }
    }
    __syncthreads();
    #pragma unroll
    for (int tt = 0; tt < 2; ++tt) {
        int c0 = (2 * p + tt) * 32;
        #pragma unroll
        for (int r = 0; r < 4; ++r) {
            int wl = ty + r * 8;
            g_xt[(((size_t)b * RES + h) * RES + (w0 + wl)) * CH + (c0 + tx)] =
                __float2half(tile[tt][tx][wl]);
        }
    }
}

// ---------------- main conv GEMM (mma.sync fp16, 2 CTAs/SM) ----------------
// CTA: M=128 (one (b,h) pixel row), N=128 (half of cout), K=2304.
// 8 warps = 2(M) x 4(N), warp tile 64x32.  3-stage 32KB ring -> 99KB smem.
#define SM_DEMOD   0              // 128 floats (this CTA's channel half)
#define SM_BIAS    512
#define SM_ST      1024
#define STAGE_SZ   32768          // A 16KB + B 16KB
#define A_OFF(s)   (SM_ST + (s) * STAGE_SZ)
#define B_OFF(s)   (SM_ST + (s) * STAGE_SZ + 16384)
#define SMEM_TOTAL (SM_ST + 3 * STAGE_SZ)     // 99328
#define SM_D       1024           // epilogue staging reuses ring

__device__ __forceinline__ void load_stage(uint32_t smem_base, int step, int slot,
                                           int b, int h, int nh, int tid) {
    int tap = step >> 2;            // 0..8
    int ic0 = (step & 3) * 64;      // channel chunk base
    int kh = tap / 3, kw = tap - kh * 3;
    int hin = h + kh - 1;
    bool hok = (unsigned)hin < RES;
    int hc = hok ? hin : 0;
    uint32_t abase = smem_base + A_OFF(slot);
    uint32_t bbase = smem_base + B_OFF(slot);
    // A: 128 rows (w) x 64 halves (128B)
    #pragma unroll
    for (int j = 0; j < 4; ++j) {
        int v = tid + j * 256;
        int row = v >> 3, seg = v & 7;
        int win = row + kw - 1;
        bool ok = hok && ((unsigned)win < RES);
        int wc = ok ? win : 0;
        const __half* src = g_xt + (((size_t)(b * RES + hc) * RES + wc) * CH
                                    + ic0 + seg * 8);
        cp16(abase + swz((uint32_t)(row * 128 + seg * 16)), src, ok ? 16u : 0u);
    }
    // B: 128 rows (cout half) x 64 halves
    #pragma unroll
    for (int j = 0; j < 4; ++j) {
        int v = tid + j * 256;
        int row = v >> 3, seg = v & 7;
        const __half* src = g_wt + ((size_t)(nh * 128 + row) * KTOT
                                    + tap * 256 + ic0 + seg * 8);
        cp16(bbase + swz((uint32_t)(row * 128 + seg * 16)), src, 16u);
    }
}

__global__ void __launch_bounds__(256, 2)
conv_gemm(const float* __restrict__ noise,
          const float* __restrict__ noise_w_p,
          const float* __restrict__ bias,
          float* __restrict__ out) {
    extern __shared__ __align__(1024) char smem[];
    uint32_t smem_base = s2u(smem);
    int tid = threadIdx.x;
    int wid = tid >> 5, lid = tid & 31;
    int wm = wid & 1, wn = wid >> 1;

    int bx = blockIdx.x;            // 4096 CTAs: b (16) x h (128) x nh (2)
    int nh = bx & 1;
    int h  = (bx >> 1) & 127;
    int b  = bx >> 8;

    // Desync co-resident CTAs (bids differing by 148 = consecutive waves):
    // odd waves start the K loop half-way round. Pure reordering of the sum.
    int S = ((bx / 148) & 1) * 18;

    float* demod_s = (float*)(smem + SM_DEMOD);
    float* bias_s  = (float*)(smem + SM_BIAS);
    if (tid < 128) {
        demod_s[tid] = g_demod[b * CH + nh * 128 + tid];
        bias_s[tid]  = bias[nh * 128 + tid];
    }

    float acc[4][4][4];
    #pragma unroll
    for (int i = 0; i < 4; ++i)
        #pragma unroll
        for (int j = 0; j < 4; ++j)
            #pragma unroll
            for (int k = 0; k < 4; ++k) acc[i][j][k] = 0.f;

    // prologue: 2 stages in flight
    {
        int s0 = S, s1 = S + 1; if (s1 >= 36) s1 -= 36;
        load_stage(smem_base, s0, 0, b, h, nh, tid); cp_commit();
        load_stage(smem_base, s1, 1, b, h, nh, tid); cp_commit();
    }

    for (int c = 0; c < 36; ++c) {
        if (c < 35) { CP_WAIT(1); } else { CP_WAIT(0); }
        __syncthreads();

        int s = c % 3;
        uint32_t abase = smem_base + A_OFF(s);
        uint32_t bbase = smem_base + B_OFF(s);

        // ---- kk = 0 first: get tensor pipe busy right after the barrier ----
        {
            uint32_t afr[4][4];
            #pragma unroll
            for (int mi = 0; mi < 4; ++mi) {
                int row = wm * 64 + mi * 16 + (lid & 15);
                int col = (lid >> 4) * 16;
                ldm4(afr[mi], abase + swz((uint32_t)(row * 128 + col)));
            }
            uint32_t bfr[2][4];
            #pragma unroll
            for (int nj = 0; nj < 2; ++nj) {
                int row = wn * 32 + nj * 16 + (lid & 7) + ((lid >> 4) << 3);
                int col = ((lid >> 3) & 1) * 16;
                ldm4(bfr[nj], bbase + swz((uint32_t)(row * 128 + col)));
            }
            #pragma unroll
            for (int mi = 0; mi < 4; ++mi)
                #pragma unroll
                for (int nj = 0; nj < 2; ++nj) {
                    mma16816(acc[mi][2 * nj],     afr[mi], bfr[nj][0], bfr[nj][1]);
                    mma16816(acc[mi][2 * nj + 1], afr[mi], bfr[nj][2], bfr[nj][3]);
                }
        }

        // ---- issue next-stage loads while kk=0 mmas drain ----
        if (c + 2 < 36) {
            int sn = c + 2 + S; if (sn >= 36) sn -= 36;
            load_stage(smem_base, sn, (c + 2) % 3, b, h, nh, tid);
            cp_commit();
        }

        // ---- kk = 1..3 ----
        #pragma unroll
        for (int kk = 1; kk < 4; ++kk) {
            uint32_t afr[4][4];
            #pragma unroll
            for (int mi = 0; mi < 4; ++mi) {
                int row = wm * 64 + mi * 16 + (lid & 15);
                int col = kk * 32 + (lid >> 4) * 16;
                ldm4(afr[mi], abase + swz((uint32_t)(row * 128 + col)));
            }
            uint32_t bfr[2][4];
            #pragma unroll
            for (int nj = 0; nj < 2; ++nj) {
                int row = wn * 32 + nj * 16 + (lid & 7) + ((lid >> 4) << 3);
                int col = kk * 32 + ((lid >> 3) & 1) * 16;
                ldm4(bfr[nj], bbase + swz((uint32_t)(row * 128 + col)));
            }
            #pragma unroll
            for (int mi = 0; mi < 4; ++mi)
                #pragma unroll
                for (int nj = 0; nj < 2; ++nj) {
                    mma16816(acc[mi][2 * nj],     afr[mi], bfr[nj][0], bfr[nj][1]);
                    mma16816(acc[mi][2 * nj + 1], afr[mi], bfr[nj][2], bfr[nj][3]);
                }
        }
    }
    __syncthreads();

    // stage D into smem as [n][m] floats (128 x 128) for coalesced NCHW output
    float* D = (float*)(smem + SM_D);
    int gq = lid >> 2, tig = lid & 3;
    #pragma unroll
    for (int mi = 0; mi < 4; ++mi) {
        int m0 = wm * 64 + mi * 16 + gq;
        #pragma unroll
        for (int ns = 0; ns < 4; ++ns) {
            int n0 = wn * 32 + ns * 8 + 2 * tig;
            float* p = acc[mi][ns];
            D[n0 * 128 + m0]           = p[0];
            D[(n0 + 1) * 128 + m0]     = p[1];
            D[n0 * 128 + m0 + 8]       = p[2];
            D[(n0 + 1) * 128 + m0 + 8] = p[3];
        }
    }
    __syncthreads();

    float nwv = noise_w_p[0];
    const float4* nz4 = (const float4*)(noise + ((size_t)b * RES + h) * RES);
    #pragma unroll 4
    for (int t = tid; t < 4096; t += 256) {       // 4096 float4 = 128n x 128m
        int n  = t >> 5;
        int m4 = (t & 31);
        float4 v  = ((const float4*)D)[t];
        float4 nz = nz4[m4];
        float dm = demod_s[n], bs = bias_s[n];
        float4 o;
        o.x = v.x * dm + nwv * nz.x + bs;
        o.y = v.y * dm + nwv * nz.y + bs;
        o.z = v.z * dm + nwv * nz.z + bs;
        o.w = v.w * dm + nwv * nz.w + bs;
        o.x = (o.x > 0.f ? o.x : 0.2f * o.x) * SQRT2F;
        o.y = (o.y > 0.f ? o.y : 0.2f * o.y) * SQRT2F;
        o.z = (o.z > 0.f ? o.z : 0.2f * o.z) * SQRT2F;
        o.w = (o.w > 0.f ? o.w : 0.2f * o.w) * SQRT2F;
        ((float4*)(out + (((size_t)b * CH + nh * 128 + n) * RES + h) * RES))[m4] = o;
    }
}

// ---------------- launch ---------------------------------------------------
extern "C" void kernel_launch(void* const* d_in, const int* in_sizes, int n_in,
                              void* d_out, int out_size) {
    const float* content = (const float*)d_in[0];
    const float* latent  = (const float*)d_in[1];
    const float* noise   = (const float*)d_in[2];
    const float* aff_w   = (const float*)d_in[3];
    const float* aff_b   = (const float*)d_in[4];
    const float* conv_w  = (const float*)d_in[5];
    const float* bias    = (const float*)d_in[6];
    const float* nw      = (const float*)d_in[7];
    float* out = (float*)d_out;

    prep_style_wsq<<<(BATCH * CH + CH * CH + 255) / 256, 256>>>(latent, aff_w, aff_b, conv_w);
    prep_demod_wt<<<BATCH + CH * 9, 256>>>(conv_w);
    mod_transpose<<<BATCH * RES * 4 * 4, 256>>>(content);

    cudaFuncSetAttribute(conv_gemm, cudaFuncAttributeMaxDynamicSharedMemorySize, SMEM_TOTAL);
    conv_gemm<<<4096, 256, SMEM_TOTAL>>>(noise, nw, bias, out);
}